// round 3
// baseline (speedup 1.0000x reference)
#include <cuda_runtime.h>
#include <math.h>
#include <stdint.h>

#define BATCH  2
#define SEQ    8192
#define DMODEL 512
#define NH     8
#define HD     64
#define DHID   2048
#define BH     (BATCH*NH)     /* 16    */
#define MROWS  (BATCH*SEQ)    /* 16384 */

/* ---------------- scratch: __device__ globals only ---------------- */
__device__ float g_q[BH*SEQ*HD];
__device__ float g_k[BH*SEQ*HD];
__device__ float g_v[BH*SEQ*HD];
__device__ float g_attn[MROWS*DMODEL];
__device__ float g_h[MROWS*DMODEL];
__device__ float g_ff1[MROWS*DHID];
__device__ float g_ff2[MROWS*DMODEL];
__device__ float g_inv[BH*SEQ];

/* =================================================================
 * FFN GEMM: MODE 0: g_ff1 = relu(g_h @ Wf1 + b)   (K=512,  N=2048)
 *           MODE 1: g_ff2 =      g_ff1 @ Wf2 + b  (K=2048, N=512)
 * 128x128x8 tiles, 8x8 per thread.
 * ================================================================= */
template<int MODE>
__global__ void __launch_bounds__(256) ffn_gemm(
    const float* __restrict__ B, const float* __restrict__ bias)
{
    constexpr int K = (MODE == 0) ? DMODEL : DHID;
    constexpr int N = (MODE == 0) ? DHID : DMODEL;
    const float* A = (MODE == 0) ? g_h   : g_ff1;
    float*       C = (MODE == 0) ? g_ff1 : g_ff2;

    __shared__ float As[8][128];
    __shared__ float Bs[8][128];
    const int tid = threadIdx.x;
    const int m0 = blockIdx.y * 128;
    const int n0 = blockIdx.x * 128;
    const int arow = tid >> 1;
    const int acol = (tid & 1) * 4;
    const int brow = tid >> 5;
    const int bcol = (tid & 31) * 4;
    const float* Aptr = A + (size_t)(m0 + arow) * K + acol;
    const float* Bptr = B + (size_t)brow * N + n0 + bcol;
    const int tx = (tid & 15) * 8;
    const int ty = (tid >> 4) * 8;

    float acc[8][8];
#pragma unroll
    for (int i = 0; i < 8; i++)
#pragma unroll
        for (int j = 0; j < 8; j++) acc[i][j] = 0.f;

    for (int k0 = 0; k0 < K; k0 += 8) {
        float4 av = *(const float4*)(Aptr + k0);
        float4 bv = *(const float4*)(Bptr + (size_t)k0 * N);
        __syncthreads();
        As[acol+0][arow] = av.x; As[acol+1][arow] = av.y;
        As[acol+2][arow] = av.z; As[acol+3][arow] = av.w;
        *(float4*)&Bs[brow][bcol] = bv;
        __syncthreads();
#pragma unroll
        for (int kk = 0; kk < 8; kk++) {
            float a[8], b[8];
            *(float4*)(a)   = *(const float4*)&As[kk][ty];
            *(float4*)(a+4) = *(const float4*)&As[kk][ty+4];
            *(float4*)(b)   = *(const float4*)&Bs[kk][tx];
            *(float4*)(b+4) = *(const float4*)&Bs[kk][tx+4];
#pragma unroll
            for (int i = 0; i < 8; i++)
#pragma unroll
                for (int j = 0; j < 8; j++)
                    acc[i][j] += a[i] * b[j];
        }
    }
#pragma unroll
    for (int i = 0; i < 8; i++) {
        int m = m0 + ty + i;
#pragma unroll
        for (int j = 0; j < 8; j += 4) {
            int n = n0 + tx + j;
            float4 r;
            r.x = acc[i][j+0] + bias[n+0];
            r.y = acc[i][j+1] + bias[n+1];
            r.z = acc[i][j+2] + bias[n+2];
            r.w = acc[i][j+3] + bias[n+3];
            if (MODE == 0) {
                r.x = fmaxf(r.x, 0.f); r.y = fmaxf(r.y, 0.f);
                r.z = fmaxf(r.z, 0.f); r.w = fmaxf(r.w, 0.f);
            }
            *(float4*)&C[(size_t)m * N + n] = r;
        }
    }
}

/* =================================================================
 * QKV projection. blockIdx.z selects q/k/v. Output per-head layout
 * [(b*NH+h)*SEQ + s]*HD + d ; q pre-scaled by 1/sqrt(HD)=0.125.
 * ================================================================= */
__global__ void __launch_bounds__(256) sgemm_qkv(
    const float* __restrict__ x,
    const float* __restrict__ Wq, const float* __restrict__ bq,
    const float* __restrict__ Wk, const float* __restrict__ bk,
    const float* __restrict__ Wv, const float* __restrict__ bv)
{
    const float* B; const float* bias; float* out; float scale;
    if (blockIdx.z == 0)      { B = Wq; bias = bq; out = g_q; scale = 0.125f; }
    else if (blockIdx.z == 1) { B = Wk; bias = bk; out = g_k; scale = 1.f; }
    else                      { B = Wv; bias = bv; out = g_v; scale = 1.f; }

    __shared__ float As[8][128];
    __shared__ float Bs[8][128];
    const int tid = threadIdx.x;
    const int m0 = blockIdx.y * 128;
    const int n0 = blockIdx.x * 128;
    const int K = DMODEL, N = DMODEL;
    const int arow = tid >> 1;
    const int acol = (tid & 1) * 4;
    const int brow = tid >> 5;
    const int bcol = (tid & 31) * 4;
    const float* Aptr = x + (size_t)(m0 + arow) * K + acol;
    const float* Bptr = B + (size_t)brow * N + n0 + bcol;
    const int tx = (tid & 15) * 8;
    const int ty = (tid >> 4) * 8;

    float acc[8][8];
#pragma unroll
    for (int i = 0; i < 8; i++)
#pragma unroll
        for (int j = 0; j < 8; j++) acc[i][j] = 0.f;

    for (int k0 = 0; k0 < K; k0 += 8) {
        float4 av = *(const float4*)(Aptr + k0);
        float4 bv = *(const float4*)(Bptr + (size_t)k0 * N);
        __syncthreads();
        As[acol+0][arow] = av.x; As[acol+1][arow] = av.y;
        As[acol+2][arow] = av.z; As[acol+3][arow] = av.w;
        *(float4*)&Bs[brow][bcol] = bv;
        __syncthreads();
#pragma unroll
        for (int kk = 0; kk < 8; kk++) {
            float a[8], b[8];
            *(float4*)(a)   = *(const float4*)&As[kk][ty];
            *(float4*)(a+4) = *(const float4*)&As[kk][ty+4];
            *(float4*)(b)   = *(const float4*)&Bs[kk][tx];
            *(float4*)(b+4) = *(const float4*)&Bs[kk][tx+4];
#pragma unroll
            for (int i = 0; i < 8; i++)
#pragma unroll
                for (int j = 0; j < 8; j++)
                    acc[i][j] += a[i] * b[j];
        }
    }
#pragma unroll
    for (int i = 0; i < 8; i++) {
        int m = m0 + ty + i;
        int bb = m >> 13;           /* / SEQ */
        int s  = m & (SEQ - 1);
#pragma unroll
        for (int j = 0; j < 8; j += 4) {
            int n = n0 + tx + j;
            int h = n >> 6;
            int d = n & 63;
            float4 r;
            r.x = (acc[i][j+0] + bias[n+0]) * scale;
            r.y = (acc[i][j+1] + bias[n+1]) * scale;
            r.z = (acc[i][j+2] + bias[n+2]) * scale;
            r.w = (acc[i][j+3] + bias[n+3]) * scale;
            *(float4*)&out[(((size_t)bb * NH + h) * SEQ + s) * HD + d] = r;
        }
    }
}

/* =================================================================
 * Sliding-window attention: one block = 64 queries of one (b,h).
 * Keys [q0-128, q0+192) in 10 tiles of 32. exp() without max-shift
 * (scores are O(1)); writes UNNORMALIZED band to out_score, keeps
 * running sum, writes normalized attn out to g_attn, 1/sum to g_inv.
 * Static smem: 43 KB.
 * ================================================================= */
__global__ void __launch_bounds__(256) attn_kernel(float* __restrict__ out_score)
{
    __shared__ float qT[64*68];   /* [d][x] transposed q                  */
    __shared__ float kT[64*34];   /* [d][y] transposed k tile (32 keys)   */
    __shared__ float vs[32*64];   /* [y][d] natural v tile                */
    __shared__ float pt[64*33];   /* [x][y] probs tile; reused as red buf */
    __shared__ float invs[64];

    const int tid = threadIdx.x;
    const int bh  = blockIdx.y;
    const int q0  = blockIdx.x * 64;
    const float* qg = g_q + (size_t)bh * SEQ * HD;
    const float* kg = g_k + (size_t)bh * SEQ * HD;
    const float* vg = g_v + (size_t)bh * SEQ * HD;

    /* load q tile transposed */
    for (int i = tid; i < 64 * 16; i += 256) {
        int row = i >> 4;
        int c4  = (i & 15) * 4;
        float4 v = *(const float4*)(qg + (size_t)(q0 + row) * HD + c4);
        qT[(c4+0)*68 + row] = v.x;
        qT[(c4+1)*68 + row] = v.y;
        qT[(c4+2)*68 + row] = v.z;
        qT[(c4+3)*68 + row] = v.w;
    }

    const int xs = (tid & 15) * 4;   /* score phase: 4 queries  */
    const int yk = (tid >> 4) * 2;   /* score phase: 2 keys     */
    const int dx = (tid & 15) * 4;   /* PV phase: 4 dims        */
    const int xr = (tid >> 4) * 4;   /* PV phase: 4 queries     */

    float acc2[4][4];
#pragma unroll
    for (int i = 0; i < 4; i++)
#pragma unroll
        for (int j = 0; j < 4; j++) acc2[i][j] = 0.f;
    float psum[4] = {0.f, 0.f, 0.f, 0.f};

    for (int t = 0; t < 10; t++) {
        __syncthreads();
        const int gbase = q0 - 128 + t * 32;
        /* load k (transposed) + v (natural) tiles */
        for (int i = tid; i < 32 * 16; i += 256) {
            int row = i >> 4;
            int c4  = (i & 15) * 4;
            int g = gbase + row;
            float4 kk = make_float4(0.f,0.f,0.f,0.f);
            float4 vv = make_float4(0.f,0.f,0.f,0.f);
            if (g >= 0 && g < SEQ) {
                kk = *(const float4*)(kg + (size_t)g * HD + c4);
                vv = *(const float4*)(vg + (size_t)g * HD + c4);
            }
            kT[(c4+0)*34 + row] = kk.x;
            kT[(c4+1)*34 + row] = kk.y;
            kT[(c4+2)*34 + row] = kk.z;
            kT[(c4+3)*34 + row] = kk.w;
            *(float4*)&vs[row*64 + c4] = vv;
        }
        __syncthreads();

        /* scores: 2 keys x 4 queries per thread */
        float acc[2][4];
#pragma unroll
        for (int i = 0; i < 2; i++)
#pragma unroll
            for (int j = 0; j < 4; j++) acc[i][j] = 0.f;
#pragma unroll 4
        for (int d = 0; d < 64; d++) {
            float2 kk = *(const float2*)&kT[d*34 + yk];
            float4 qv = *(const float4*)&qT[d*68 + xs];
            acc[0][0] += kk.x * qv.x;  acc[0][1] += kk.x * qv.y;
            acc[0][2] += kk.x * qv.z;  acc[0][3] += kk.x * qv.w;
            acc[1][0] += kk.y * qv.x;  acc[1][1] += kk.y * qv.y;
            acc[1][2] += kk.y * qv.z;  acc[1][3] += kk.y * qv.w;
        }
        /* exp + mask, stage to pt, accumulate row sums */
#pragma unroll
        for (int i = 0; i < 2; i++) {
            int ylocal = t*32 + yk + i;
            int g = q0 - 128 + ylocal;
#pragma unroll
            for (int j = 0; j < 4; j++) {
                int x = xs + j;
                int jb = ylocal - x;
                float e = 0.f;
                if (jb >= 0 && jb <= 256 && g >= 0 && g < SEQ)
                    e = expf(acc[i][j]);
                pt[x*33 + yk + i] = e;
                psum[j] += e;
            }
        }
        __syncthreads();

        /* band write (unnormalized) */
        {
            float* osc = out_score + ((size_t)bh * SEQ + q0) * 257;
            for (int i = tid; i < 64 * 32; i += 256) {
                int q = i >> 5;
                int k = i & 31;
                int jb = t*32 + k - q;
                if (jb >= 0 && jb <= 256)
                    osc[(size_t)q * 257 + jb] = pt[q*33 + k];
            }
        }
        /* O += P @ V (unnormalized) */
#pragma unroll 4
        for (int yy = 0; yy < 32; yy++) {
            float4 v4 = *(const float4*)&vs[yy*64 + dx];
            float a0 = pt[(xr+0)*33 + yy];
            float a1 = pt[(xr+1)*33 + yy];
            float a2 = pt[(xr+2)*33 + yy];
            float a3 = pt[(xr+3)*33 + yy];
            acc2[0][0] += a0*v4.x; acc2[0][1] += a0*v4.y; acc2[0][2] += a0*v4.z; acc2[0][3] += a0*v4.w;
            acc2[1][0] += a1*v4.x; acc2[1][1] += a1*v4.y; acc2[1][2] += a1*v4.z; acc2[1][3] += a1*v4.w;
            acc2[2][0] += a2*v4.x; acc2[2][1] += a2*v4.y; acc2[2][2] += a2*v4.z; acc2[2][3] += a2*v4.w;
            acc2[3][0] += a3*v4.x; acc2[3][1] += a3*v4.y; acc2[3][2] += a3*v4.z; acc2[3][3] += a3*v4.w;
        }
    }

    /* row-sum reduction (reuse pt as [16][64]) */
    __syncthreads();
#pragma unroll
    for (int j = 0; j < 4; j++)
        pt[(tid >> 4)*64 + xs + j] = psum[j];
    __syncthreads();
    if (tid < 64) {
        float s = 0.f;
        for (int r = 0; r < 16; r++) s += pt[r*64 + tid];
        float iv = 1.f / s;
        invs[tid] = iv;
        g_inv[(size_t)bh * SEQ + q0 + tid] = iv;
    }
    __syncthreads();

    const int bb = bh >> 3;
    const int hh = bh & 7;
#pragma unroll
    for (int i = 0; i < 4; i++) {
        float iv = invs[xr + i];
        float4 r = make_float4(acc2[i][0]*iv, acc2[i][1]*iv,
                               acc2[i][2]*iv, acc2[i][3]*iv);
        *(float4*)&g_attn[((size_t)bb * SEQ + q0 + xr + i) * DMODEL + hh*HD + dx] = r;
    }
}

/* normalize band in place */
__global__ void __launch_bounds__(128) band_norm(float* __restrict__ out_score)
{
    const int row = blockIdx.x;
    const float iv = g_inv[row];
    float* p = out_score + (size_t)row * 257;
    for (int t = threadIdx.x; t < 257; t += 128)
        p[t] *= iv;
}

/* =================================================================
 * LayerNorm(a + b): MODE 0: g_h = LN(g_attn + x)
 *                   MODE 1: out = LN(g_ff2 + g_h)
 * ================================================================= */
template<int MODE>
__global__ void __launch_bounds__(128) ln_res(
    const float* __restrict__ xb,
    const float* __restrict__ gam, const float* __restrict__ bet,
    float* __restrict__ outp)
{
    const float* a = (MODE == 0) ? g_attn : g_ff2;
    const float* b = (MODE == 0) ? xb     : g_h;
    float* out     = (MODE == 0) ? g_h    : outp;

    __shared__ float sred[2][4];
    const int row = blockIdx.x;
    const int tid = threadIdx.x;
    const float4 va = ((const float4*)(a + (size_t)row * DMODEL))[tid];
    const float4 vb = ((const float4*)(b + (size_t)row * DMODEL))[tid];
    float4 v = make_float4(va.x+vb.x, va.y+vb.y, va.z+vb.z, va.w+vb.w);
    float s  = v.x + v.y + v.z + v.w;
    float sq = v.x*v.x + v.y*v.y + v.z*v.z + v.w*v.w;
#pragma unroll
    for (int o = 16; o > 0; o >>= 1) {
        s  += __shfl_down_sync(0xFFFFFFFFu, s,  o);
        sq += __shfl_down_sync(0xFFFFFFFFu, sq, o);
    }
    if ((tid & 31) == 0) { sred[0][tid >> 5] = s; sred[1][tid >> 5] = sq; }
    __syncthreads();
    s  = sred[0][0] + sred[0][1] + sred[0][2] + sred[0][3];
    sq = sred[1][0] + sred[1][1] + sred[1][2] + sred[1][3];
    float mean = s * (1.f / DMODEL);
    float var  = sq * (1.f / DMODEL) - mean * mean;
    float rs   = rsqrtf(var + 1e-5f);
    float4 g4 = ((const float4*)gam)[tid];
    float4 b4 = ((const float4*)bet)[tid];
    float4 r;
    r.x = (v.x - mean) * rs * g4.x + b4.x;
    r.y = (v.y - mean) * rs * g4.y + b4.y;
    r.z = (v.z - mean) * rs * g4.z + b4.z;
    r.w = (v.w - mean) * rs * g4.w + b4.w;
    ((float4*)(out + (size_t)row * DMODEL))[tid] = r;
}

/* ================================================================= */
extern "C" void kernel_launch(void* const* d_in, const int* in_sizes, int n_in,
                              void* d_out, int out_size)
{
    const float* x    = (const float*)d_in[0];
    const float* Wq   = (const float*)d_in[1];
    const float* bq   = (const float*)d_in[2];
    const float* Wk   = (const float*)d_in[3];
    const float* bk   = (const float*)d_in[4];
    const float* Wv   = (const float*)d_in[5];
    const float* bv   = (const float*)d_in[6];
    const float* ln1g = (const float*)d_in[7];
    const float* ln1b = (const float*)d_in[8];
    const float* Wf1  = (const float*)d_in[9];
    const float* bf1  = (const float*)d_in[10];
    const float* Wf2  = (const float*)d_in[11];
    const float* bf2  = (const float*)d_in[12];
    const float* ln2g = (const float*)d_in[13];
    const float* ln2b = (const float*)d_in[14];
    (void)in_sizes; (void)n_in; (void)out_size;

    float* out       = (float*)d_out;                    /* [16384,512]   */
    float* out_score = out + (size_t)MROWS * DMODEL;     /* [16,8192,257] */

    /* 1. QKV projections */
    sgemm_qkv<<<dim3(DMODEL/128, MROWS/128, 3), 256>>>(x, Wq, bq, Wk, bk, Wv, bv);
    /* 2. attention (unnormalized band + normalized attn out) */
    attn_kernel<<<dim3(SEQ/64, BH), 256>>>(out_score);
    /* 3. normalize band */
    band_norm<<<BH*SEQ, 128>>>(out_score);
    /* 4. h = LN(attn + x) */
    ln_res<0><<<MROWS, 128>>>(x, ln1g, ln1b, nullptr);
    /* 5. ff1 = relu(h @ Wf1 + bf1) */
    ffn_gemm<0><<<dim3(DHID/128, MROWS/128), 256>>>(Wf1, bf1);
    /* 6. ff2 = ff1 @ Wf2 + bf2 */
    ffn_gemm<1><<<dim3(DMODEL/128, MROWS/128), 256>>>(Wf2, bf2);
    /* 7. out = LN(ff2 + h) */
    ln_res<1><<<MROWS, 128>>>(x, ln2g, ln2b, out);
}

// round 6
// speedup vs baseline: 2.1667x; 2.1667x over previous
#include <cuda_runtime.h>
#include <math.h>
#include <stdint.h>

#define BATCH  2
#define SEQ    8192
#define DMODEL 512
#define NH     8
#define HD     64
#define DHID   2048
#define BH     (BATCH*NH)     /* 16    */
#define MROWS  (BATCH*SEQ)    /* 16384 */

/* ---------------- scratch: __device__ globals only ---------------- */
__device__ float g_q[BH*SEQ*HD];
__device__ float g_k[BH*SEQ*HD];
__device__ float g_v[BH*SEQ*HD];
__device__ float g_attn[MROWS*DMODEL];
__device__ float g_h[MROWS*DMODEL];
__device__ float g_ff1[MROWS*DHID];
__device__ float g_ff2[MROWS*DMODEL];
__device__ float g_inv[BH*SEQ];

__device__ __forceinline__ uint32_t cvt_tf32(float x) {
    uint32_t r; asm("cvt.rna.tf32.f32 %0, %1;" : "=r"(r) : "f"(x)); return r;
}
__device__ __forceinline__ void mma_tf32(
    float& c0, float& c1, float& c2, float& c3,
    uint32_t a0, uint32_t a1, uint32_t a2, uint32_t a3,
    uint32_t b0, uint32_t b1)
{
    asm volatile(
        "mma.sync.aligned.m16n8k8.row.col.f32.tf32.tf32.f32 "
        "{%0,%1,%2,%3}, {%4,%5,%6,%7}, {%8,%9}, {%0,%1,%2,%3};"
        : "+f"(c0), "+f"(c1), "+f"(c2), "+f"(c3)
        : "r"(a0), "r"(a1), "r"(a2), "r"(a3), "r"(b0), "r"(b1));
}

#define PA 36    /* A smem pitch (floats): banks (4m+k)%32 conflict-free   */
#define PB 136   /* B smem pitch (floats): banks (8k+n)%32 conflict-free   */
#define BK 32

/* =================================================================
 * tf32 warp-MMA GEMM, tile 128x128x32, 256 thr (2x4 warps, 64x32 warp tile)
 * MODE 0: QKV (blockIdx.z selects q/k/v; A=x, per-head epilogue)
 * MODE 1: FFN1 g_ff1 = relu(g_h @ Wf1 + b)
 * MODE 2: FFN2 g_ff2 = g_ff1 @ Wf2 + b
 * ================================================================= */
template<int MODE>
__global__ void __launch_bounds__(256) mma_gemm(
    const float* __restrict__ x,
    const float* __restrict__ W0, const float* __restrict__ b0,
    const float* __restrict__ W1, const float* __restrict__ b1,
    const float* __restrict__ W2, const float* __restrict__ b2)
{
    constexpr int N = (MODE == 1) ? DHID : DMODEL;
    constexpr int K = (MODE == 2) ? DHID : DMODEL;
    constexpr int NIT = K / BK;

    __shared__ uint32_t sA[128 * PA];   /* [m][k] tf32 bits */
    __shared__ uint32_t sB[BK * PB];    /* [k][n] tf32 bits */

    const int tid  = threadIdx.x;
    const int wid  = tid >> 5;
    const int lane = tid & 31;
    const int gr   = lane >> 2;     /* group id   */
    const int tg   = lane & 3;      /* in-group   */
    const int wm   = wid & 1;       /* warp m: 0/1  -> 64 rows   */
    const int wn   = wid >> 1;      /* warp n: 0..3 -> 32 cols   */
    const int m0   = blockIdx.y * 128;
    const int n0   = blockIdx.x * 128;

    const float* Ag; const float* Bg; const float* bias;
    if (MODE == 0) {
        Ag = x;
        if (blockIdx.z == 0)      { Bg = W0; bias = b0; }
        else if (blockIdx.z == 1) { Bg = W1; bias = b1; }
        else                      { Bg = W2; bias = b2; }
    } else if (MODE == 1) { Ag = g_h;   Bg = W0; bias = b0; }
    else                  { Ag = g_ff1; Bg = W0; bias = b0; }

    float acc[4][4][4];
#pragma unroll
    for (int i = 0; i < 4; i++)
#pragma unroll
        for (int j = 0; j < 4; j++)
#pragma unroll
            for (int r = 0; r < 4; r++) acc[i][j][r] = 0.f;

    /* staging registers for global tiles */
    float4 ra[4], rb[4];

    /* prologue: load tile 0 */
#pragma unroll
    for (int i = 0; i < 4; i++) {
        int idx = i * 256 + tid;
        int row = idx >> 3, c4 = idx & 7;
        ra[i] = *(const float4*)(Ag + (size_t)(m0 + row) * K + c4 * 4);
    }
#pragma unroll
    for (int i = 0; i < 4; i++) {
        int idx = i * 256 + tid;
        int row = idx >> 5, c4 = idx & 31;
        rb[i] = *(const float4*)(Bg + (size_t)row * N + n0 + c4 * 4);
    }

    for (int it = 0; it < NIT; it++) {
        /* store staged tile to smem (tf32-rounded) */
#pragma unroll
        for (int i = 0; i < 4; i++) {
            int idx = i * 256 + tid;
            int row = idx >> 3, c4 = idx & 7;
            uint32_t* p = &sA[row * PA + c4 * 4];
            p[0] = cvt_tf32(ra[i].x); p[1] = cvt_tf32(ra[i].y);
            p[2] = cvt_tf32(ra[i].z); p[3] = cvt_tf32(ra[i].w);
        }
#pragma unroll
        for (int i = 0; i < 4; i++) {
            int idx = i * 256 + tid;
            int row = idx >> 5, c4 = idx & 31;
            uint32_t* p = &sB[row * PB + c4 * 4];
            p[0] = cvt_tf32(rb[i].x); p[1] = cvt_tf32(rb[i].y);
            p[2] = cvt_tf32(rb[i].z); p[3] = cvt_tf32(rb[i].w);
        }
        __syncthreads();

        /* issue next tile's global loads (latency overlaps compute) */
        if (it + 1 < NIT) {
            const int k0 = (it + 1) * BK;
#pragma unroll
            for (int i = 0; i < 4; i++) {
                int idx = i * 256 + tid;
                int row = idx >> 3, c4 = idx & 7;
                ra[i] = *(const float4*)(Ag + (size_t)(m0 + row) * K + k0 + c4 * 4);
            }
#pragma unroll
            for (int i = 0; i < 4; i++) {
                int idx = i * 256 + tid;
                int row = idx >> 5, c4 = idx & 31;
                rb[i] = *(const float4*)(Bg + (size_t)(k0 + row) * N + n0 + c4 * 4);
            }
        }

        /* compute: 4 k-frags of 8 */
#pragma unroll
        for (int kf = 0; kf < 4; kf++) {
            uint32_t a[4][4], b[4][2];
#pragma unroll
            for (int mf = 0; mf < 4; mf++) {
                const uint32_t* ap = &sA[(wm*64 + mf*16 + gr) * PA + kf*8 + tg];
                a[mf][0] = ap[0];
                a[mf][1] = ap[8 * PA];
                a[mf][2] = ap[4];
                a[mf][3] = ap[8 * PA + 4];
            }
#pragma unroll
            for (int nf = 0; nf < 4; nf++) {
                const uint32_t* bp = &sB[(kf*8 + tg) * PB + wn*32 + nf*8 + gr];
                b[nf][0] = bp[0];
                b[nf][1] = bp[4 * PB];
            }
#pragma unroll
            for (int mf = 0; mf < 4; mf++)
#pragma unroll
                for (int nf = 0; nf < 4; nf++)
                    mma_tf32(acc[mf][nf][0], acc[mf][nf][1],
                             acc[mf][nf][2], acc[mf][nf][3],
                             a[mf][0], a[mf][1], a[mf][2], a[mf][3],
                             b[nf][0], b[nf][1]);
        }
        __syncthreads();
    }

    /* ---------------- epilogue ---------------- */
#pragma unroll
    for (int mf = 0; mf < 4; mf++) {
#pragma unroll
        for (int nf = 0; nf < 4; nf++) {
            int mrow = m0 + wm*64 + mf*16 + gr;
            int ncol = n0 + wn*32 + nf*8 + 2*tg;
            float bx = bias[ncol], by = bias[ncol+1];
            float2 r0 = make_float2(acc[mf][nf][0] + bx, acc[mf][nf][1] + by);
            float2 r1 = make_float2(acc[mf][nf][2] + bx, acc[mf][nf][3] + by);
            if (MODE == 0) {
                const float scale = (blockIdx.z == 0) ? 0.125f : 1.f;
                float* outp = (blockIdx.z == 0) ? g_q
                            : ((blockIdx.z == 1) ? g_k : g_v);
                r0.x *= scale; r0.y *= scale; r1.x *= scale; r1.y *= scale;
                int h = ncol >> 6, d = ncol & 63;
                {
                    int bb = mrow >> 13, s = mrow & (SEQ-1);
                    *(float2*)&outp[(((size_t)bb*NH + h)*SEQ + s)*HD + d] = r0;
                }
                {
                    int m2 = mrow + 8;
                    int bb = m2 >> 13, s = m2 & (SEQ-1);
                    *(float2*)&outp[(((size_t)bb*NH + h)*SEQ + s)*HD + d] = r1;
                }
            } else {
                float* Cg = (MODE == 1) ? g_ff1 : g_ff2;
                if (MODE == 1) {
                    r0.x = fmaxf(r0.x, 0.f); r0.y = fmaxf(r0.y, 0.f);
                    r1.x = fmaxf(r1.x, 0.f); r1.y = fmaxf(r1.y, 0.f);
                }
                *(float2*)&Cg[(size_t)mrow * N + ncol] = r0;
                *(float2*)&Cg[(size_t)(mrow+8) * N + ncol] = r1;
            }
        }
    }
}

/* =================================================================
 * Sliding-window attention (unchanged, passing version)
 * ================================================================= */
__global__ void __launch_bounds__(256) attn_kernel(float* __restrict__ out_score)
{
    __shared__ float qT[64*68];
    __shared__ float kT[64*34];
    __shared__ float vs[32*64];
    __shared__ float pt[64*33];
    __shared__ float invs[64];

    const int tid = threadIdx.x;
    const int bh  = blockIdx.y;
    const int q0  = blockIdx.x * 64;
    const float* qg = g_q + (size_t)bh * SEQ * HD;
    const float* kg = g_k + (size_t)bh * SEQ * HD;
    const float* vg = g_v + (size_t)bh * SEQ * HD;

    for (int i = tid; i < 64 * 16; i += 256) {
        int row = i >> 4;
        int c4  = (i & 15) * 4;
        float4 v = *(const float4*)(qg + (size_t)(q0 + row) * HD + c4);
        qT[(c4+0)*68 + row] = v.x;
        qT[(c4+1)*68 + row] = v.y;
        qT[(c4+2)*68 + row] = v.z;
        qT[(c4+3)*68 + row] = v.w;
    }

    const int xs = (tid & 15) * 4;
    const int yk = (tid >> 4) * 2;
    const int dx = (tid & 15) * 4;
    const int xr = (tid >> 4) * 4;

    float acc2[4][4];
#pragma unroll
    for (int i = 0; i < 4; i++)
#pragma unroll
        for (int j = 0; j < 4; j++) acc2[i][j] = 0.f;
    float psum[4] = {0.f, 0.f, 0.f, 0.f};

    for (int t = 0; t < 10; t++) {
        __syncthreads();
        const int gbase = q0 - 128 + t * 32;
        for (int i = tid; i < 32 * 16; i += 256) {
            int row = i >> 4;
            int c4  = (i & 15) * 4;
            int g = gbase + row;
            float4 kk = make_float4(0.f,0.f,0.f,0.f);
            float4 vv = make_float4(0.f,0.f,0.f,0.f);
            if (g >= 0 && g < SEQ) {
                kk = *(const float4*)(kg + (size_t)g * HD + c4);
                vv = *(const float4*)(vg + (size_t)g * HD + c4);
            }
            kT[(c4+0)*34 + row] = kk.x;
            kT[(c4+1)*34 + row] = kk.y;
            kT[(c4+2)*34 + row] = kk.z;
            kT[(c4+3)*34 + row] = kk.w;
            *(float4*)&vs[row*64 + c4] = vv;
        }
        __syncthreads();

        float acc[2][4];
#pragma unroll
        for (int i = 0; i < 2; i++)
#pragma unroll
            for (int j = 0; j < 4; j++) acc[i][j] = 0.f;
#pragma unroll 4
        for (int d = 0; d < 64; d++) {
            float2 kk = *(const float2*)&kT[d*34 + yk];
            float4 qv = *(const float4*)&qT[d*68 + xs];
            acc[0][0] += kk.x * qv.x;  acc[0][1] += kk.x * qv.y;
            acc[0][2] += kk.x * qv.z;  acc[0][3] += kk.x * qv.w;
            acc[1][0] += kk.y * qv.x;  acc[1][1] += kk.y * qv.y;
            acc[1][2] += kk.y * qv.z;  acc[1][3] += kk.y * qv.w;
        }
#pragma unroll
        for (int i = 0; i < 2; i++) {
            int ylocal = t*32 + yk + i;
            int g = q0 - 128 + ylocal;
#pragma unroll
            for (int j = 0; j < 4; j++) {
                int xq = xs + j;
                int jb = ylocal - xq;
                float e = 0.f;
                if (jb >= 0 && jb <= 256 && g >= 0 && g < SEQ)
                    e = expf(acc[i][j]);
                pt[xq*33 + yk + i] = e;
                psum[j] += e;
            }
        }
        __syncthreads();

        {
            float* osc = out_score + ((size_t)bh * SEQ + q0) * 257;
            for (int i = tid; i < 64 * 32; i += 256) {
                int q = i >> 5;
                int k = i & 31;
                int jb = t*32 + k - q;
                if (jb >= 0 && jb <= 256)
                    osc[(size_t)q * 257 + jb] = pt[q*33 + k];
            }
        }
#pragma unroll 4
        for (int yy = 0; yy < 32; yy++) {
            float4 v4 = *(const float4*)&vs[yy*64 + dx];
            float a0 = pt[(xr+0)*33 + yy];
            float a1 = pt[(xr+1)*33 + yy];
            float a2 = pt[(xr+2)*33 + yy];
            float a3 = pt[(xr+3)*33 + yy];
            acc2[0][0] += a0*v4.x; acc2[0][1] += a0*v4.y; acc2[0][2] += a0*v4.z; acc2[0][3] += a0*v4.w;
            acc2[1][0] += a1*v4.x; acc2[1][1] += a1*v4.y; acc2[1][2] += a1*v4.z; acc2[1][3] += a1*v4.w;
            acc2[2][0] += a2*v4.x; acc2[2][1] += a2*v4.y; acc2[2][2] += a2*v4.z; acc2[2][3] += a2*v4.w;
            acc2[3][0] += a3*v4.x; acc2[3][1] += a3*v4.y; acc2[3][2] += a3*v4.z; acc2[3][3] += a3*v4.w;
        }
    }

    __syncthreads();
#pragma unroll
    for (int j = 0; j < 4; j++)
        pt[(tid >> 4)*64 + xs + j] = psum[j];
    __syncthreads();
    if (tid < 64) {
        float s = 0.f;
        for (int r = 0; r < 16; r++) s += pt[r*64 + tid];
        float iv = 1.f / s;
        invs[tid] = iv;
        g_inv[(size_t)bh * SEQ + q0 + tid] = iv;
    }
    __syncthreads();

    const int bb = bh >> 3;
    const int hh = bh & 7;
#pragma unroll
    for (int i = 0; i < 4; i++) {
        float iv = invs[xr + i];
        float4 r = make_float4(acc2[i][0]*iv, acc2[i][1]*iv,
                               acc2[i][2]*iv, acc2[i][3]*iv);
        *(float4*)&g_attn[((size_t)bb * SEQ + q0 + xr + i) * DMODEL + hh*HD + dx] = r;
    }
}

__global__ void __launch_bounds__(128) band_norm(float* __restrict__ out_score)
{
    const int row = blockIdx.x;
    const float iv = g_inv[row];
    float* p = out_score + (size_t)row * 257;
    for (int t = threadIdx.x; t < 257; t += 128)
        p[t] *= iv;
}

template<int MODE>
__global__ void __launch_bounds__(128) ln_res(
    const float* __restrict__ xb,
    const float* __restrict__ gam, const float* __restrict__ bet,
    float* __restrict__ outp)
{
    const float* a = (MODE == 0) ? g_attn : g_ff2;
    const float* b = (MODE == 0) ? xb     : g_h;
    float* out     = (MODE == 0) ? g_h    : outp;

    __shared__ float sred[2][4];
    const int row = blockIdx.x;
    const int tid = threadIdx.x;
    const float4 va = ((const float4*)(a + (size_t)row * DMODEL))[tid];
    const float4 vb = ((const float4*)(b + (size_t)row * DMODEL))[tid];
    float4 v = make_float4(va.x+vb.x, va.y+vb.y, va.z+vb.z, va.w+vb.w);
    float s  = v.x + v.y + v.z + v.w;
    float sq = v.x*v.x + v.y*v.y + v.z*v.z + v.w*v.w;
#pragma unroll
    for (int o = 16; o > 0; o >>= 1) {
        s  += __shfl_down_sync(0xFFFFFFFFu, s,  o);
        sq += __shfl_down_sync(0xFFFFFFFFu, sq, o);
    }
    if ((tid & 31) == 0) { sred[0][tid >> 5] = s; sred[1][tid >> 5] = sq; }
    __syncthreads();
    s  = sred[0][0] + sred[0][1] + sred[0][2] + sred[0][3];
    sq = sred[1][0] + sred[1][1] + sred[1][2] + sred[1][3];
    float mean = s * (1.f / DMODEL);
    float var  = sq * (1.f / DMODEL) - mean * mean;
    float rs   = rsqrtf(var + 1e-5f);
    float4 g4 = ((const float4*)gam)[tid];
    float4 b4 = ((const float4*)bet)[tid];
    float4 r;
    r.x = (v.x - mean) * rs * g4.x + b4.x;
    r.y = (v.y - mean) * rs * g4.y + b4.y;
    r.z = (v.z - mean) * rs * g4.z + b4.z;
    r.w = (v.w - mean) * rs * g4.w + b4.w;
    ((float4*)(out + (size_t)row * DMODEL))[tid] = r;
}

/* ================================================================= */
extern "C" void kernel_launch(void* const* d_in, const int* in_sizes, int n_in,
                              void* d_out, int out_size)
{
    const float* x    = (const float*)d_in[0];
    const float* Wq   = (const float*)d_in[1];
    const float* bq   = (const float*)d_in[2];
    const float* Wk   = (const float*)d_in[3];
    const float* bk   = (const float*)d_in[4];
    const float* Wv   = (const float*)d_in[5];
    const float* bv   = (const float*)d_in[6];
    const float* ln1g = (const float*)d_in[7];
    const float* ln1b = (const float*)d_in[8];
    const float* Wf1  = (const float*)d_in[9];
    const float* bf1  = (const float*)d_in[10];
    const float* Wf2  = (const float*)d_in[11];
    const float* bf2  = (const float*)d_in[12];
    const float* ln2g = (const float*)d_in[13];
    const float* ln2b = (const float*)d_in[14];
    (void)in_sizes; (void)n_in; (void)out_size;

    float* out       = (float*)d_out;                    /* [16384,512]   */
    float* out_score = out + (size_t)MROWS * DMODEL;     /* [16,8192,257] */

    /* 1. QKV projections (tf32 warp-MMA) */
    mma_gemm<0><<<dim3(DMODEL/128, MROWS/128, 3), 256>>>(
        x, Wq, bq, Wk, bk, Wv, bv);
    /* 2. attention */
    attn_kernel<<<dim3(SEQ/64, BH), 256>>>(out_score);
    /* 3. normalize band */
    band_norm<<<BH*SEQ, 128>>>(out_score);
    /* 4. h = LN(attn + x) */
    ln_res<0><<<MROWS, 128>>>(x, ln1g, ln1b, nullptr);
    /* 5. ff1 = relu(h @ Wf1 + bf1) */
    mma_gemm<1><<<dim3(DHID/128, MROWS/128), 256>>>(
        nullptr, Wf1, bf1, nullptr, nullptr, nullptr, nullptr);
    /* 6. ff2 = ff1 @ Wf2 + bf2 */
    mma_gemm<2><<<dim3(DMODEL/128, MROWS/128), 256>>>(
        nullptr, Wf2, bf2, nullptr, nullptr, nullptr, nullptr);
    /* 7. out = LN(ff2 + h) */
    ln_res<1><<<MROWS, 128>>>(x, ln2g, ln2b, out);
}

// round 9
// speedup vs baseline: 2.2601x; 1.0431x over previous
#include <cuda_runtime.h>
#include <math.h>
#include <stdint.h>

#define BATCH  2
#define SEQ    8192
#define DMODEL 512
#define NH     8
#define HD     64
#define DHID   2048
#define BH     (BATCH*NH)     /* 16    */
#define MROWS  (BATCH*SEQ)    /* 16384 */

/* ---------------- scratch: __device__ globals only ---------------- */
__device__ float g_q[BH*SEQ*HD];
__device__ float g_k[BH*SEQ*HD];
__device__ float g_v[BH*SEQ*HD];
__device__ float g_attn[MROWS*DMODEL];
__device__ float g_h[MROWS*DMODEL];
__device__ float g_ff1[MROWS*DHID];
__device__ float g_ff2[MROWS*DMODEL];
__device__ float g_inv[BH*SEQ];

__device__ __forceinline__ uint32_t smem_u32(const void* p) {
    uint32_t a;
    asm("{ .reg .u64 t; cvta.to.shared.u64 t, %1; cvt.u32.u64 %0, t; }"
        : "=r"(a) : "l"(p));
    return a;
}
__device__ __forceinline__ uint32_t cvt_tf32(float x) {
    uint32_t r; asm("cvt.rna.tf32.f32 %0, %1;" : "=r"(r) : "f"(x)); return r;
}
__device__ __forceinline__ void mma_tf32(
    float& c0, float& c1, float& c2, float& c3,
    uint32_t a0, uint32_t a1, uint32_t a2, uint32_t a3,
    uint32_t b0, uint32_t b1)
{
    asm volatile(
        "mma.sync.aligned.m16n8k8.row.col.f32.tf32.tf32.f32 "
        "{%0,%1,%2,%3}, {%4,%5,%6,%7}, {%8,%9}, {%0,%1,%2,%3};"
        : "+f"(c0), "+f"(c1), "+f"(c2), "+f"(c3)
        : "r"(a0), "r"(a1), "r"(a2), "r"(a3), "r"(b0), "r"(b1));
}
__device__ __forceinline__ void cp16(uint32_t dst, const void* src) {
    asm volatile("cp.async.cg.shared.global [%0], [%1], 16;"
                 :: "r"(dst), "l"(src));
}
#define CP_COMMIT() asm volatile("cp.async.commit_group;" ::: "memory")
#define CP_WAIT1()  asm volatile("cp.async.wait_group 1;" ::: "memory")

#define PA 20    /* A smem pitch: banks (20*gr+tg)%32 distinct over warp  */
#define PB 136   /* B smem pitch: banks (8*tg+gr)%32 distinct over warp   */
#define BK 16
#define STG_FLOATS (128*PA + BK*PB)            /* 4736 floats            */
/* static smem: 2 stages * 18944 B = 37888 B  (<48KB, no attr needed)    */

/* =================================================================
 * tf32 warp-MMA GEMM, tile 128x128x16, 256 thr (2x4 warps, 64x32 warp
 * tile), 2-stage cp.async pipeline, ALL-STATIC smem, no host attr calls.
 * MODE 0: QKV (blockIdx.z selects q/k/v; A=x, per-head epilogue)
 * MODE 1: FFN1 g_ff1 = relu(g_h @ Wf1 + b)
 * MODE 2: FFN2 g_ff2 = g_ff1 @ Wf2 + b
 * ================================================================= */
template<int MODE>
__global__ void __launch_bounds__(256) mma_gemm(
    const float* __restrict__ x,
    const float* __restrict__ W0, const float* __restrict__ b0,
    const float* __restrict__ W1, const float* __restrict__ b1,
    const float* __restrict__ W2, const float* __restrict__ b2)
{
    constexpr int N = (MODE == 1) ? DHID : DMODEL;
    constexpr int K = (MODE == 2) ? DHID : DMODEL;
    constexpr int NIT = K / BK;

    __shared__ float smp[2 * STG_FLOATS];
    const uint32_t sbase = smem_u32(smp);

    const int tid  = threadIdx.x;
    const int wid  = tid >> 5;
    const int lane = tid & 31;
    const int gr   = lane >> 2;
    const int tg   = lane & 3;
    const int wm   = wid & 1;
    const int wn   = wid >> 1;
    const int m0   = blockIdx.y * 128;
    const int n0   = blockIdx.x * 128;

    const float* Ag; const float* Bg; const float* bias;
    if (MODE == 0) {
        Ag = x;
        if (blockIdx.z == 0)      { Bg = W0; bias = b0; }
        else if (blockIdx.z == 1) { Bg = W1; bias = b1; }
        else                      { Bg = W2; bias = b2; }
    } else if (MODE == 1) { Ag = g_h;   Bg = W0; bias = b0; }
    else                  { Ag = g_ff1; Bg = W0; bias = b0; }

    float acc[4][4][4];
#pragma unroll
    for (int i = 0; i < 4; i++)
#pragma unroll
        for (int j = 0; j < 4; j++)
#pragma unroll
            for (int r = 0; r < 4; r++) acc[i][j][r] = 0.f;

    /* A copy slots: 512 float4 chunks (128 rows x 4); 2 per thread.
       B copy slots: 512 float4 chunks (16 rows x 32); 2 per thread.  */
    const int arow0 = tid >> 2,  ac4 = (tid & 3);          /* +64 rows  */
    const int brow0 = tid >> 5,  bc4 = (tid & 31);         /* +8 rows   */

#define ISSUE(cc, ss)                                                        \
    do {                                                                     \
        const int _k0 = (cc) * BK;                                           \
        const uint32_t _ab = sbase + (uint32_t)((ss) * STG_FLOATS) * 4u;     \
        const uint32_t _bb = _ab + (uint32_t)(128 * PA) * 4u;                \
        cp16(_ab + (uint32_t)(arow0 * PA + ac4 * 4) * 4u,                    \
             Ag + (size_t)(m0 + arow0) * K + _k0 + ac4 * 4);                 \
        cp16(_ab + (uint32_t)((arow0 + 64) * PA + ac4 * 4) * 4u,             \
             Ag + (size_t)(m0 + arow0 + 64) * K + _k0 + ac4 * 4);            \
        cp16(_bb + (uint32_t)(brow0 * PB + bc4 * 4) * 4u,                    \
             Bg + (size_t)(_k0 + brow0) * N + n0 + bc4 * 4);                 \
        cp16(_bb + (uint32_t)((brow0 + 8) * PB + bc4 * 4) * 4u,              \
             Bg + (size_t)(_k0 + brow0 + 8) * N + n0 + bc4 * 4);             \
    } while (0)

    /* prologue */
    ISSUE(0, 0);
    CP_COMMIT();

    for (int c = 0; c < NIT; c++) {
        if (c + 1 < NIT)
            ISSUE(c + 1, (c + 1) & 1);
        CP_COMMIT();                 /* one group per iter (maybe empty) */
        CP_WAIT1();                  /* chunk c resident                 */
        __syncthreads();

        const float* sA = smp + (c & 1) * STG_FLOATS;
        const float* sB = sA + 128 * PA;

#pragma unroll
        for (int kf = 0; kf < 2; kf++) {
            uint32_t a[4][4], b[4][2];
#pragma unroll
            for (int mf = 0; mf < 4; mf++) {
                const float* ap = &sA[(wm*64 + mf*16 + gr) * PA + kf*8 + tg];
                a[mf][0] = cvt_tf32(ap[0]);
                a[mf][1] = cvt_tf32(ap[8 * PA]);
                a[mf][2] = cvt_tf32(ap[4]);
                a[mf][3] = cvt_tf32(ap[8 * PA + 4]);
            }
#pragma unroll
            for (int nf = 0; nf < 4; nf++) {
                const float* bp = &sB[(kf*8 + tg) * PB + wn*32 + nf*8 + gr];
                b[nf][0] = cvt_tf32(bp[0]);
                b[nf][1] = cvt_tf32(bp[4 * PB]);
            }
#pragma unroll
            for (int mf = 0; mf < 4; mf++)
#pragma unroll
                for (int nf = 0; nf < 4; nf++)
                    mma_tf32(acc[mf][nf][0], acc[mf][nf][1],
                             acc[mf][nf][2], acc[mf][nf][3],
                             a[mf][0], a[mf][1], a[mf][2], a[mf][3],
                             b[nf][0], b[nf][1]);
        }
        __syncthreads();
    }
#undef ISSUE

    /* ---------------- epilogue ---------------- */
#pragma unroll
    for (int mf = 0; mf < 4; mf++) {
#pragma unroll
        for (int nf = 0; nf < 4; nf++) {
            int mrow = m0 + wm*64 + mf*16 + gr;
            int ncol = n0 + wn*32 + nf*8 + 2*tg;
            float bx = bias[ncol], by = bias[ncol+1];
            float2 r0 = make_float2(acc[mf][nf][0] + bx, acc[mf][nf][1] + by);
            float2 r1 = make_float2(acc[mf][nf][2] + bx, acc[mf][nf][3] + by);
            if (MODE == 0) {
                const float scale = (blockIdx.z == 0) ? 0.125f : 1.f;
                float* outp = (blockIdx.z == 0) ? g_q
                            : ((blockIdx.z == 1) ? g_k : g_v);
                r0.x *= scale; r0.y *= scale; r1.x *= scale; r1.y *= scale;
                int h = ncol >> 6, d = ncol & 63;
                {
                    int bb = mrow >> 13, s = mrow & (SEQ-1);
                    *(float2*)&outp[(((size_t)bb*NH + h)*SEQ + s)*HD + d] = r0;
                }
                {
                    int m2 = mrow + 8;
                    int bb = m2 >> 13, s = m2 & (SEQ-1);
                    *(float2*)&outp[(((size_t)bb*NH + h)*SEQ + s)*HD + d] = r1;
                }
            } else {
                float* Cg = (MODE == 1) ? g_ff1 : g_ff2;
                if (MODE == 1) {
                    r0.x = fmaxf(r0.x, 0.f); r0.y = fmaxf(r0.y, 0.f);
                    r1.x = fmaxf(r1.x, 0.f); r1.y = fmaxf(r1.y, 0.f);
                }
                *(float2*)&Cg[(size_t)mrow * N + ncol] = r0;
                *(float2*)&Cg[(size_t)(mrow+8) * N + ncol] = r1;
            }
        }
    }
}

/* =================================================================
 * Sliding-window attention (unchanged, passing version)
 * ================================================================= */
__global__ void __launch_bounds__(256) attn_kernel(float* __restrict__ out_score)
{
    __shared__ float qT[64*68];
    __shared__ float kT[64*34];
    __shared__ float vs[32*64];
    __shared__ float pt[64*33];
    __shared__ float invs[64];

    const int tid = threadIdx.x;
    const int bh  = blockIdx.y;
    const int q0  = blockIdx.x * 64;
    const float* qg = g_q + (size_t)bh * SEQ * HD;
    const float* kg = g_k + (size_t)bh * SEQ * HD;
    const float* vg = g_v + (size_t)bh * SEQ * HD;

    for (int i = tid; i < 64 * 16; i += 256) {
        int row = i >> 4;
        int c4  = (i & 15) * 4;
        float4 v = *(const float4*)(qg + (size_t)(q0 + row) * HD + c4);
        qT[(c4+0)*68 + row] = v.x;
        qT[(c4+1)*68 + row] = v.y;
        qT[(c4+2)*68 + row] = v.z;
        qT[(c4+3)*68 + row] = v.w;
    }

    const int xs = (tid & 15) * 4;
    const int yk = (tid >> 4) * 2;
    const int dx = (tid & 15) * 4;
    const int xr = (tid >> 4) * 4;

    float acc2[4][4];
#pragma unroll
    for (int i = 0; i < 4; i++)
#pragma unroll
        for (int j = 0; j < 4; j++) acc2[i][j] = 0.f;
    float psum[4] = {0.f, 0.f, 0.f, 0.f};

    for (int t = 0; t < 10; t++) {
        __syncthreads();
        const int gbase = q0 - 128 + t * 32;
        for (int i = tid; i < 32 * 16; i += 256) {
            int row = i >> 4;
            int c4  = (i & 15) * 4;
            int g = gbase + row;
            float4 kk = make_float4(0.f,0.f,0.f,0.f);
            float4 vv = make_float4(0.f,0.f,0.f,0.f);
            if (g >= 0 && g < SEQ) {
                kk = *(const float4*)(kg + (size_t)g * HD + c4);
                vv = *(const float4*)(vg + (size_t)g * HD + c4);
            }
            kT[(c4+0)*34 + row] = kk.x;
            kT[(c4+1)*34 + row] = kk.y;
            kT[(c4+2)*34 + row] = kk.z;
            kT[(c4+3)*34 + row] = kk.w;
            *(float4*)&vs[row*64 + c4] = vv;
        }
        __syncthreads();

        float acc[2][4];
#pragma unroll
        for (int i = 0; i < 2; i++)
#pragma unroll
            for (int j = 0; j < 4; j++) acc[i][j] = 0.f;
#pragma unroll 4
        for (int d = 0; d < 64; d++) {
            float2 kk = *(const float2*)&kT[d*34 + yk];
            float4 qv = *(const float4*)&qT[d*68 + xs];
            acc[0][0] += kk.x * qv.x;  acc[0][1] += kk.x * qv.y;
            acc[0][2] += kk.x * qv.z;  acc[0][3] += kk.x * qv.w;
            acc[1][0] += kk.y * qv.x;  acc[1][1] += kk.y * qv.y;
            acc[1][2] += kk.y * qv.z;  acc[1][3] += kk.y * qv.w;
        }
#pragma unroll
        for (int i = 0; i < 2; i++) {
            int ylocal = t*32 + yk + i;
            int g = q0 - 128 + ylocal;
#pragma unroll
            for (int j = 0; j < 4; j++) {
                int xq = xs + j;
                int jb = ylocal - xq;
                float e = 0.f;
                if (jb >= 0 && jb <= 256 && g >= 0 && g < SEQ)
                    e = expf(acc[i][j]);
                pt[xq*33 + yk + i] = e;
                psum[j] += e;
            }
        }
        __syncthreads();

        {
            float* osc = out_score + ((size_t)bh * SEQ + q0) * 257;
            for (int i = tid; i < 64 * 32; i += 256) {
                int q = i >> 5;
                int k = i & 31;
                int jb = t*32 + k - q;
                if (jb >= 0 && jb <= 256)
                    osc[(size_t)q * 257 + jb] = pt[q*33 + k];
            }
        }
#pragma unroll 4
        for (int yy = 0; yy < 32; yy++) {
            float4 v4 = *(const float4*)&vs[yy*64 + dx];
            float a0 = pt[(xr+0)*33 + yy];
            float a1 = pt[(xr+1)*33 + yy];
            float a2 = pt[(xr+2)*33 + yy];
            float a3 = pt[(xr+3)*33 + yy];
            acc2[0][0] += a0*v4.x; acc2[0][1] += a0*v4.y; acc2[0][2] += a0*v4.z; acc2[0][3] += a0*v4.w;
            acc2[1][0] += a1*v4.x; acc2[1][1] += a1*v4.y; acc2[1][2] += a1*v4.z; acc2[1][3] += a1*v4.w;
            acc2[2][0] += a2*v4.x; acc2[2][1] += a2*v4.y; acc2[2][2] += a2*v4.z; acc2[2][3] += a2*v4.w;
            acc2[3][0] += a3*v4.x; acc2[3][1] += a3*v4.y; acc2[3][2] += a3*v4.z; acc2[3][3] += a3*v4.w;
        }
    }

    __syncthreads();
#pragma unroll
    for (int j = 0; j < 4; j++)
        pt[(tid >> 4)*64 + xs + j] = psum[j];
    __syncthreads();
    if (tid < 64) {
        float s = 0.f;
        for (int r = 0; r < 16; r++) s += pt[r*64 + tid];
        float iv = 1.f / s;
        invs[tid] = iv;
        g_inv[(size_t)bh * SEQ + q0 + tid] = iv;
    }
    __syncthreads();

    const int bb = bh >> 3;
    const int hh = bh & 7;
#pragma unroll
    for (int i = 0; i < 4; i++) {
        float iv = invs[xr + i];
        float4 r = make_float4(acc2[i][0]*iv, acc2[i][1]*iv,
                               acc2[i][2]*iv, acc2[i][3]*iv);
        *(float4*)&g_attn[((size_t)bb * SEQ + q0 + xr + i) * DMODEL + hh*HD + dx] = r;
    }
}

__global__ void __launch_bounds__(128) band_norm(float* __restrict__ out_score)
{
    const int row = blockIdx.x;
    const float iv = g_inv[row];
    float* p = out_score + (size_t)row * 257;
    for (int t = threadIdx.x; t < 257; t += 128)
        p[t] *= iv;
}

template<int MODE>
__global__ void __launch_bounds__(128) ln_res(
    const float* __restrict__ xb,
    const float* __restrict__ gam, const float* __restrict__ bet,
    float* __restrict__ outp)
{
    const float* a = (MODE == 0) ? g_attn : g_ff2;
    const float* b = (MODE == 0) ? xb     : g_h;
    float* out     = (MODE == 0) ? g_h    : outp;

    __shared__ float sred[2][4];
    const int row = blockIdx.x;
    const int tid = threadIdx.x;
    const float4 va = ((const float4*)(a + (size_t)row * DMODEL))[tid];
    const float4 vb = ((const float4*)(b + (size_t)row * DMODEL))[tid];
    float4 v = make_float4(va.x+vb.x, va.y+vb.y, va.z+vb.z, va.w+vb.w);
    float s  = v.x + v.y + v.z + v.w;
    float sq = v.x*v.x + v.y*v.y + v.z*v.z + v.w*v.w;
#pragma unroll
    for (int o = 16; o > 0; o >>= 1) {
        s  += __shfl_down_sync(0xFFFFFFFFu, s,  o);
        sq += __shfl_down_sync(0xFFFFFFFFu, sq, o);
    }
    if ((tid & 31) == 0) { sred[0][tid >> 5] = s; sred[1][tid >> 5] = sq; }
    __syncthreads();
    s  = sred[0][0] + sred[0][1] + sred[0][2] + sred[0][3];
    sq = sred[1][0] + sred[1][1] + sred[1][2] + sred[1][3];
    float mean = s * (1.f / DMODEL);
    float var  = sq * (1.f / DMODEL) - mean * mean;
    float rs   = rsqrtf(var + 1e-5f);
    float4 g4 = ((const float4*)gam)[tid];
    float4 b4 = ((const float4*)bet)[tid];
    float4 r;
    r.x = (v.x - mean) * rs * g4.x + b4.x;
    r.y = (v.y - mean) * rs * g4.y + b4.y;
    r.z = (v.z - mean) * rs * g4.z + b4.z;
    r.w = (v.w - mean) * rs * g4.w + b4.w;
    ((float4*)(out + (size_t)row * DMODEL))[tid] = r;
}

/* ================================================================= */
extern "C" void kernel_launch(void* const* d_in, const int* in_sizes, int n_in,
                              void* d_out, int out_size)
{
    const float* x    = (const float*)d_in[0];
    const float* Wq   = (const float*)d_in[1];
    const float* bq   = (const float*)d_in[2];
    const float* Wk   = (const float*)d_in[3];
    const float* bk   = (const float*)d_in[4];
    const float* Wv   = (const float*)d_in[5];
    const float* bv   = (const float*)d_in[6];
    const float* ln1g = (const float*)d_in[7];
    const float* ln1b = (const float*)d_in[8];
    const float* Wf1  = (const float*)d_in[9];
    const float* bf1  = (const float*)d_in[10];
    const float* Wf2  = (const float*)d_in[11];
    const float* bf2  = (const float*)d_in[12];
    const float* ln2g = (const float*)d_in[13];
    const float* ln2b = (const float*)d_in[14];
    (void)in_sizes; (void)n_in; (void)out_size;

    float* out       = (float*)d_out;                    /* [16384,512]   */
    float* out_score = out + (size_t)MROWS * DMODEL;     /* [16,8192,257] */

    /* 1. QKV projections (tf32 warp-MMA, 2-stage cp.async, static smem) */
    mma_gemm<0><<<dim3(DMODEL/128, MROWS/128, 3), 256>>>(
        x, Wq, bq, Wk, bk, Wv, bv);
    /* 2. attention */
    attn_kernel<<<dim3(SEQ/64, BH), 256>>>(out_score);
    /* 3. normalize band */
    band_norm<<<BH*SEQ, 128>>>(out_score);
    /* 4. h = LN(attn + x) */
    ln_res<0><<<MROWS, 128>>>(x, ln1g, ln1b, nullptr);
    /* 5. ff1 = relu(h @ Wf1 + bf1) */
    mma_gemm<1><<<dim3(DHID/128, MROWS/128), 256>>>(
        nullptr, Wf1, bf1, nullptr, nullptr, nullptr, nullptr);
    /* 6. ff2 = ff1 @ Wf2 + bf2 */
    mma_gemm<2><<<dim3(DMODEL/128, MROWS/128), 256>>>(
        nullptr, Wf2, bf2, nullptr, nullptr, nullptr, nullptr);
    /* 7. out = LN(ff2 + h) */
    ln_res<1><<<MROWS, 128>>>(x, ln2g, ln2b, out);
}